// round 7
// baseline (speedup 1.0000x reference)
#include <cuda_runtime.h>
#include <math.h>

// ---------------- problem constants ----------------
#define BB 4
#define LL 2048
#define DD 128
#define MM (BB*LL)          // 8192 rows
#define PER_B (DD*LL)       // 262144 elements per batch per [D][L] buffer
#define TOT (BB*PER_B)      // 1048576

typedef unsigned long long u64;

// ---------------- scratch (static device memory; no allocation) ----------------
__device__ float g_pk[TOT];     // projection outputs [b][l][d] == conv input [b][c][s]
__device__ float g_pq[TOT];
__device__ float g_pv[TOT];
__device__ float g_ck[TOT];     // conv+silu outputs [b][c][s]
__device__ float g_cq[TOT];
__device__ float g_cv[TOT];
__device__ float g_kT[TOT];     // normalized, transposed [b][t][c]
__device__ float g_qT[TOT];
__device__ float g_vT[TOT];
__device__ float g_dT[TOT];     // delta output [b][t][c]
__device__ float g_normed[TOT]; // rms-normalized delta
__device__ float g_beta[MM];
__device__ float g_kq[MM];      // k_t . q_t per (b,t)
__device__ float g_ninv[2*512]; // inv l2 norms for k (0..511) and q (512..1023)

__device__ __forceinline__ float wsum(float v) {
    #pragma unroll
    for (int o = 16; o > 0; o >>= 1) v += __shfl_xor_sync(0xffffffffu, v, o);
    return v;
}

// ---------------- tf32 helpers ----------------
__device__ __forceinline__ unsigned f2tf32(float x) {
    unsigned r; asm("cvt.rna.tf32.f32 %0, %1;" : "=r"(r) : "f"(x)); return r;
}
__device__ __forceinline__ void mma_tf32(float c[4], const unsigned a[4],
                                         unsigned b0, unsigned b1) {
    asm("mma.sync.aligned.m16n8k8.row.col.f32.tf32.tf32.f32 "
        "{%0,%1,%2,%3}, {%4,%5,%6,%7}, {%8,%9}, {%0,%1,%2,%3};"
        : "+f"(c[0]), "+f"(c[1]), "+f"(c[2]), "+f"(c[3])
        : "r"(a[0]), "r"(a[1]), "r"(a[2]), "r"(a[3]), "r"(b0), "r"(b1));
}
__device__ __forceinline__ void split_sts4(unsigned* dH, unsigned* dL, float4 v) {
    uint4 h, l;
    h.x = f2tf32(v.x); l.x = f2tf32(v.x - __uint_as_float(h.x));
    h.y = f2tf32(v.y); l.y = f2tf32(v.y - __uint_as_float(h.y));
    h.z = f2tf32(v.z); l.z = f2tf32(v.z - __uint_as_float(h.z));
    h.w = f2tf32(v.w); l.w = f2tf32(v.w - __uint_as_float(h.w));
    *(uint4*)dH = h; *(uint4*)dL = l;
}
__device__ __forceinline__ void split_sts2(unsigned* dH, unsigned* dL, float2 v) {
    uint2 h, l;
    h.x = f2tf32(v.x); l.x = f2tf32(v.x - __uint_as_float(h.x));
    h.y = f2tf32(v.y); l.y = f2tf32(v.y - __uint_as_float(h.y));
    *(uint2*)dH = h; *(uint2*)dL = l;
}

// =====================================================================
// 3xTF32 tensor-core GEMM core, 256 threads (8 warps).
// C[128, 64] block tile = A[m0:+128, :K] @ B[0:64, :K]^T + bias.
// 8 warps (4m x 2n), warp tile 32x32 (m16n8k8 tiles 2x4, 3 mma terms).
// BK=8, smem rows padded to 12 words, hi/lo tf32 split at staging,
// double-buffered.
// =====================================================================
__device__ __forceinline__ void gemm3tf32_core256(
    const float* __restrict__ A, int lda,
    const float* __restrict__ Bw, int ldb,
    const float* __restrict__ bias,
    float* __restrict__ C, int ldc,
    int m0, int nkt)
{
    __shared__ unsigned AsH[2][128*12], AsL[2][128*12];
    __shared__ unsigned BsH[2][64*12],  BsL[2][64*12];

    const int tid  = threadIdx.x;
    const int w    = tid >> 5, lane = tid & 31;
    const int wm   = w & 3,  wn = w >> 2;         // 4 m-tiles x 2 n-tiles
    const int g    = lane >> 2, tg = lane & 3;

    float acc[2][4][4];
    #pragma unroll
    for (int i = 0; i < 2; i++)
        #pragma unroll
        for (int j = 0; j < 4; j++)
            #pragma unroll
            for (int c = 0; c < 4; c++) acc[i][j][c] = 0.f;

    // staging mapping: A row = tid&127, k-half = (tid>>7)*4 (float4)
    const int arw = tid & 127, ahf = (tid >> 7) * 4;
    const float* arow = A + (size_t)(m0 + arw) * lda + ahf;
    // B row = tid>>2 (0..63), k-pair = (tid&3)*2 (float2)
    const int bn = tid >> 2, bc = (tid & 3) * 2;
    const float* brow = Bw + (size_t)bn * ldb + bc;

    // stage kt=0 into buf 0
    float4 af = *(const float4*)(arow);
    float2 bf = *(const float2*)(brow);
    split_sts4(&AsH[0][arw*12 + ahf], &AsL[0][arw*12 + ahf], af);
    split_sts2(&BsH[0][bn*12 + bc],   &BsL[0][bn*12 + bc],   bf);
    __syncthreads();

    for (int kt = 0; kt < nkt; ++kt) {
        const int buf = kt & 1;
        if (kt + 1 < nkt) {
            af = *(const float4*)(arow + (kt + 1) * 8);
            bf = *(const float2*)(brow + (kt + 1) * 8);
        }
        // A fragments (hi & lo), 2 m16 tiles
        unsigned ah[2][4], al[2][4];
        #pragma unroll
        for (int i = 0; i < 2; i++) {
            int r0 = (wm*32 + i*16 + g) * 12 + tg;
            int r1 = r0 + 96;   // +8 rows
            ah[i][0] = AsH[buf][r0];   ah[i][1] = AsH[buf][r1];
            ah[i][2] = AsH[buf][r0+4]; ah[i][3] = AsH[buf][r1+4];
            al[i][0] = AsL[buf][r0];   al[i][1] = AsL[buf][r1];
            al[i][2] = AsL[buf][r0+4]; al[i][3] = AsL[buf][r1+4];
        }
        #pragma unroll
        for (int j = 0; j < 4; j++) {
            int nn = (wn*32 + j*8 + g) * 12 + tg;
            unsigned bh0 = BsH[buf][nn], bh1 = BsH[buf][nn+4];
            unsigned bl0 = BsL[buf][nn], bl1 = BsL[buf][nn+4];
            #pragma unroll
            for (int i = 0; i < 2; i++) {
                mma_tf32(acc[i][j], al[i], bh0, bh1);  // Alo*Bhi
                mma_tf32(acc[i][j], ah[i], bl0, bl1);  // Ahi*Blo
                mma_tf32(acc[i][j], ah[i], bh0, bh1);  // Ahi*Bhi
            }
        }
        if (kt + 1 < nkt) {
            const int nb = buf ^ 1;
            split_sts4(&AsH[nb][arw*12 + ahf], &AsL[nb][arw*12 + ahf], af);
            split_sts2(&BsH[nb][bn*12 + bc],   &BsL[nb][bn*12 + bc],   bf);
            __syncthreads();
        }
    }
    // epilogue
    #pragma unroll
    for (int i = 0; i < 2; i++) {
        const int r = m0 + wm*32 + i*16 + g;
        #pragma unroll
        for (int j = 0; j < 4; j++) {
            const int col = wn*32 + j*8 + tg*2;
            const float b0v = bias[col], b1v = bias[col + 1];
            float2 o0 = make_float2(acc[i][j][0] + b0v, acc[i][j][1] + b1v);
            float2 o1 = make_float2(acc[i][j][2] + b0v, acc[i][j][3] + b1v);
            *(float2*)(C + (size_t)r * ldc + col)       = o0;
            *(float2*)(C + (size_t)(r + 8) * ldc + col) = o1;
        }
    }
}

// Kernel 1: fused k/q/v projection GEMM, tensor cores. grid (6, 64) x 256.
__global__ void __launch_bounds__(256) gemm_proj_tf32(
    const float* __restrict__ X,
    const float* __restrict__ Wk, const float* __restrict__ Wq, const float* __restrict__ Wv,
    const float* __restrict__ bk, const float* __restrict__ bq, const float* __restrict__ bv)
{
    const int sel = blockIdx.x >> 1;
    const int d0  = (blockIdx.x & 1) * 64;
    const float* W    = (sel == 0) ? Wk : (sel == 1) ? Wq : Wv;
    const float* bias = (sel == 0) ? bk : (sel == 1) ? bq : bv;
    float* C          = (sel == 0) ? g_pk : (sel == 1) ? g_pq : g_pv;
    gemm3tf32_core256(X, 2048, W + (size_t)d0 * 2048, 2048, bias + d0, C + d0, 128,
                      blockIdx.y * 128, 256);
}

// Kernel 8: output GEMM, tensor cores. grid (32, 64) x 256.
__global__ void __launch_bounds__(256) gemm_out_tf32(
    const float* __restrict__ Wo, const float* __restrict__ bo, float* __restrict__ OUT)
{
    const int n0 = blockIdx.x * 64;
    gemm3tf32_core256(g_normed, 128, Wo + (size_t)n0 * 128, 128, bo + n0, OUT + n0, 2048,
                      blockIdx.y * 128, 16);
}

// =====================================================================
// Kernel 2: beta = sigmoid(x @ beta_w^T + beta_b). One warp per row.
// =====================================================================
__global__ void __launch_bounds__(128) beta_kernel(
    const float* __restrict__ X, const float* __restrict__ bw, const float* __restrict__ bb,
    int m_off)
{
    const int m = m_off + blockIdx.x * 4 + (threadIdx.x >> 5);
    const int lane = threadIdx.x & 31;
    const float4* xr = (const float4*)(X + (size_t)m * 2048);
    const float4* wr = (const float4*)bw;
    float s = 0.f;
    #pragma unroll 4
    for (int i = 0; i < 16; i++) {
        float4 a = xr[i * 32 + lane];
        float4 w = wr[i * 32 + lane];
        s += a.x * w.x + a.y * w.y + a.z * w.z + a.w * w.w;
    }
    s = wsum(s);
    if (lane == 0) g_beta[m] = 1.f / (1.f + expf(-(s + bb[0])));
}

// =====================================================================
// Kernel 3: 1-D conv (k=3 over s, 128->128 ch) + bias + silu.
// =====================================================================
__global__ void __launch_bounds__(256) conv_silu(
    const float* __restrict__ wk, const float* __restrict__ bk,
    const float* __restrict__ wq, const float* __restrict__ bq,
    const float* __restrict__ wv, const float* __restrict__ bv)
{
    const int arr = blockIdx.z >> 2;
    const int b   = blockIdx.z & 3;
    const float* in  = (arr == 0) ? g_pk : (arr == 1) ? g_pq : g_pv;
    float* out       = (arr == 0) ? g_ck : (arr == 1) ? g_cq : g_cv;
    const float* w   = (arr == 0) ? wk : (arr == 1) ? wq : wv;
    const float* bias= (arr == 0) ? bk : (arr == 1) ? bq : bv;

    const int s0 = blockIdx.x * 128;
    const int o0 = blockIdx.y * 64;
    __shared__ float sin_[16][130];
    __shared__ float swt[64][16][3];
    const int tid = threadIdx.x;
    const int to = tid >> 4, ts = tid & 15;
    const int o_loc = to * 4, s_loc = ts * 8;
    const float* inb = in + (size_t)b * PER_B;

    float acc[4][8];
    #pragma unroll
    for (int oo = 0; oo < 4; oo++)
        #pragma unroll
        for (int ss = 0; ss < 8; ss++) acc[oo][ss] = 0.f;

    for (int ic = 0; ic < 8; ic++) {
        for (int i = tid; i < 2080; i += 256) {
            int j = i / 130, p = i % 130;
            int gs = s0 + p - 1;
            sin_[j][p] = (gs >= 0 && gs < 2048) ? inb[(ic * 16 + j) * 2048 + gs] : 0.f;
        }
        for (int i = tid; i < 3072; i += 256) {
            int o = i / 48, rr = i % 48, j = rr / 3, kh = rr % 3;
            swt[o][j][kh] = w[((size_t)(o0 + o) * 128 + ic * 16 + j) * 9 + kh * 3 + 1];
        }
        __syncthreads();
        #pragma unroll
        for (int j = 0; j < 16; j++) {
            float xin[10];
            #pragma unroll
            for (int p = 0; p < 10; p++) xin[p] = sin_[j][s_loc + p];
            #pragma unroll
            for (int oo = 0; oo < 4; oo++) {
                float w0 = swt[o_loc + oo][j][0];
                float w1 = swt[o_loc + oo][j][1];
                float w2 = swt[o_loc + oo][j][2];
                #pragma unroll
                for (int ss = 0; ss < 8; ss++)
                    acc[oo][ss] = fmaf(w0, xin[ss],
                                   fmaf(w1, xin[ss + 1],
                                    fmaf(w2, xin[ss + 2], acc[oo][ss])));
            }
        }
        __syncthreads();
    }
    float* outb = out + (size_t)b * PER_B;
    #pragma unroll
    for (int oo = 0; oo < 4; oo++) {
        float bvv = bias[o0 + o_loc + oo];
        float* orow = outb + (size_t)(o0 + o_loc + oo) * 2048 + s0 + s_loc;
        #pragma unroll
        for (int ss = 0; ss < 8; ss++) {
            float y = acc[oo][ss] + bvv;
            orow[ss] = y / (1.f + expf(-y));
        }
    }
}

// =====================================================================
// Kernel 4: inverse L2 norms over the s axis (2048) for k and q rows.
// =====================================================================
__global__ void __launch_bounds__(128) l2norms()
{
    const int arr = blockIdx.y;
    const int idx = blockIdx.x;
    const float* in = ((arr == 0) ? g_ck : g_cq) + (size_t)idx * 2048;
    const int tid = threadIdx.x;
    float ss = 0.f;
    const float4* in4 = (const float4*)in;
    for (int i = tid; i < 512; i += 128) {
        float4 v = in4[i];
        ss += v.x * v.x + v.y * v.y + v.z * v.z + v.w * v.w;
    }
    ss = wsum(ss);
    __shared__ float red[4];
    if ((tid & 31) == 0) red[tid >> 5] = ss;
    __syncthreads();
    if (tid == 0) {
        float tot = red[0] + red[1] + red[2] + red[3];
        g_ninv[arr * 512 + idx] = 1.f / fmaxf(sqrtf(tot), 1e-12f);
    }
}

// =====================================================================
// Kernel 5: scale (k,q) + transpose all three to [b][t][c].
// =====================================================================
__global__ void transpose_scale()
{
    const int z = blockIdx.z;
    const int arr = z >> 2, b = z & 3;
    const float* in = (arr == 0) ? g_ck : (arr == 1) ? g_cq : g_cv;
    float* out      = (arr == 0) ? g_kT : (arr == 1) ? g_qT : g_vT;
    const int s0 = blockIdx.x * 32, c0 = blockIdx.y * 32;
    __shared__ float tile[32][33];
    const int tx = threadIdx.x, ty = threadIdx.y;
    #pragma unroll
    for (int i = 0; i < 4; i++) {
        int c = c0 + ty + i * 8;
        float sc = (arr < 2) ? g_ninv[arr * 512 + b * 128 + c] : 1.f;
        tile[ty + i * 8][tx] = in[(size_t)b * PER_B + (size_t)c * 2048 + s0 + tx] * sc;
    }
    __syncthreads();
    #pragma unroll
    for (int i = 0; i < 4; i++) {
        int s = s0 + ty + i * 8;
        out[(size_t)b * PER_B + (size_t)s * 128 + c0 + tx] = tile[tx][ty + i * 8];
    }
}

// =====================================================================
// Kernel 5b: kq[m] = k_t . q_t (normalized). One warp per row.
// =====================================================================
__global__ void __launch_bounds__(128) kq_kernel()
{
    const int m = blockIdx.x * 4 + (threadIdx.x >> 5);
    const int lane = threadIdx.x & 31;
    const float* kr = g_kT + (size_t)m * 128;
    const float* qr = g_qT + (size_t)m * 128;
    float s = kr[lane] * qr[lane];
    s = fmaf(kr[lane + 32], qr[lane + 32], s);
    s = fmaf(kr[lane + 64], qr[lane + 64], s);
    s = fmaf(kr[lane + 96], qr[lane + 96], s);
    s = wsum(s);
    if (lane == 0) g_kq[m] = s;
}

// =====================================================================
// Kernel 6: delta rule. One warp per (b, row r); lane holds
// S[r][lane + 32j]. o_r = S_old[r].q + u_r*(k.q) keeps the two
// reductions independent -> interleaved shfl trees. 128 blocks x 128 thr.
// =====================================================================
__global__ void __launch_bounds__(128) delta_kernel()
{
    const int b  = blockIdx.x >> 5;
    const int rg = blockIdx.x & 31;
    const int warp = threadIdx.x >> 5;
    const int lane = threadIdx.x & 31;
    const int r = rg * 4 + warp;

    const float* kb = g_kT + (size_t)b * PER_B;
    const float* qb = g_qT + (size_t)b * PER_B;
    const float* vb = g_vT + (size_t)b * PER_B;
    const float* bbp = g_beta + b * 2048;
    const float* kqp = g_kq + b * 2048;
    float* ob = g_dT + (size_t)b * PER_B;

    float s0 = 0.f, s1 = 0.f, s2 = 0.f, s3 = 0.f;
    float kc0 = kb[lane], kc1 = kb[lane + 32], kc2 = kb[lane + 64], kc3 = kb[lane + 96];
    float qc0 = qb[lane], qc1 = qb[lane + 32], qc2 = qb[lane + 64], qc3 = qb[lane + 96];
    float vc = vb[r];
    float bc = bbp[0];
    float kqc = kqp[0];

    for (int t = 0; t < 2048; ++t) {
        float kn0 = 0, kn1 = 0, kn2 = 0, kn3 = 0, qn0 = 0, qn1 = 0, qn2 = 0, qn3 = 0;
        float vn = 0, bn = 0, kqn = 0;
        if (t < 2047) {
            const float* kp = kb + (size_t)(t + 1) * 128;
            const float* qp = qb + (size_t)(t + 1) * 128;
            kn0 = kp[lane]; kn1 = kp[lane + 32]; kn2 = kp[lane + 64]; kn3 = kp[lane + 96];
            qn0 = qp[lane]; qn1 = qp[lane + 32]; qn2 = qp[lane + 64]; qn3 = qp[lane + 96];
            vn = vb[(size_t)(t + 1) * 128 + r];
            bn = bbp[t + 1];
            kqn = kqp[t + 1];
        }
        float pa = fmaf(kc1, s1, kc0 * s0);
        float pb = fmaf(kc3, s3, kc2 * s2);
        float p  = pa + pb;
        float da = fmaf(qc1, s1, qc0 * s0);
        float db = fmaf(qc3, s3, qc2 * s2);
        float d  = da + db;
        #pragma unroll
        for (int o = 16; o > 0; o >>= 1) {
            p += __shfl_xor_sync(0xffffffffu, p, o);
            d += __shfl_xor_sync(0xffffffffu, d, o);
        }
        float u = bc * (vc - p);
        float oo = fmaf(u, kqc, d);
        if (lane == 0) ob[(size_t)t * 128 + r] = oo;
        s0 = fmaf(u, kc0, s0); s1 = fmaf(u, kc1, s1);
        s2 = fmaf(u, kc2, s2); s3 = fmaf(u, kc3, s3);

        kc0 = kn0; kc1 = kn1; kc2 = kn2; kc3 = kn3;
        qc0 = qn0; qc1 = qn1; qc2 = qn2; qc3 = qn3;
        vc = vn; bc = bn; kqc = kqn;
    }
}

// =====================================================================
// Kernel 7: RMS normalize delta over D * rms_w.
// =====================================================================
__global__ void __launch_bounds__(128) rms_kernel(const float* __restrict__ rms_w)
{
    const int m = blockIdx.x * 4 + (threadIdx.x >> 5);
    const int lane = threadIdx.x & 31;
    const float* row = g_dT + (size_t)m * 128;
    float v0 = row[lane], v1 = row[lane + 32], v2 = row[lane + 64], v3 = row[lane + 96];
    float ss = v0 * v0 + v1 * v1 + v2 * v2 + v3 * v3;
    ss = wsum(ss);
    float rs = 1.f / sqrtf(ss * (1.f / 128.f) + 1.1920928955078125e-07f);
    float* o = g_normed + (size_t)m * 128;
    o[lane]      = v0 * rs * rms_w[lane];
    o[lane + 32] = v1 * rs * rms_w[lane + 32];
    o[lane + 64] = v2 * rs * rms_w[lane + 64];
    o[lane + 96] = v3 * rs * rms_w[lane + 96];
}

// =====================================================================
extern "C" void kernel_launch(void* const* d_in, const int* in_sizes, int n_in,
                              void* d_out, int out_size)
{
    const float* x    = (const float*)d_in[0];
    const float* kpw  = (const float*)d_in[1];
    const float* kpb  = (const float*)d_in[2];
    const float* qpw  = (const float*)d_in[3];
    const float* qpb  = (const float*)d_in[4];
    const float* vpw  = (const float*)d_in[5];
    const float* vpb  = (const float*)d_in[6];
    const float* kcw  = (const float*)d_in[7];
    const float* kcb  = (const float*)d_in[8];
    const float* qcw  = (const float*)d_in[9];
    const float* qcb  = (const float*)d_in[10];
    const float* vcw  = (const float*)d_in[11];
    const float* vcb  = (const float*)d_in[12];
    const float* bw   = (const float*)d_in[13];
    const float* bb   = (const float*)d_in[14];
    const float* rmsw = (const float*)d_in[15];
    const float* ow   = (const float*)d_in[16];
    const float* obias= (const float*)d_in[17];
    float* out = (float*)d_out;

    // beta split into 3 launches so the ncu-profiled slot lands on the
    // projection GEMM (verify the occupancy prediction directly).
    beta_kernel<<<512, 128>>>(x, bw, bb, 0);
    beta_kernel<<<512, 128>>>(x, bw, bb, 2048);
    beta_kernel<<<1024, 128>>>(x, bw, bb, 4096);
    gemm_proj_tf32<<<dim3(6, 64), 256>>>(x, kpw, qpw, vpw, kpb, qpb, vpb);
    conv_silu<<<dim3(16, 2, 12), 256>>>(kcw, kcb, qcw, qcb, vcw, vcb);
    l2norms<<<dim3(512, 2), 128>>>();
    transpose_scale<<<dim3(64, 4, 12), dim3(32, 8)>>>();
    kq_kernel<<<2048, 128>>>();
    delta_kernel<<<128, 128>>>();
    rms_kernel<<<2048, 128>>>(rmsw);
    gemm_out_tf32<<<dim3(32, 64), 256>>>(ow, obias, out);
}

// round 8
// speedup vs baseline: 1.1483x; 1.1483x over previous
#include <cuda_runtime.h>
#include <math.h>

// ---------------- problem constants ----------------
#define BB 4
#define LL 2048
#define DD 128
#define MM (BB*LL)          // 8192 rows
#define PER_B (DD*LL)       // 262144 elements per batch per [D][L] buffer
#define TOT (BB*PER_B)      // 1048576

typedef unsigned long long u64;

// ---------------- scratch (static device memory; no allocation) ----------------
__device__ float g_pk[TOT];     // projection outputs [b][l][d] == conv input [b][c][s]
__device__ float g_pq[TOT];
__device__ float g_pv[TOT];
__device__ float g_psum[2][3][TOT]; // split-K partials [z][sel]
__device__ float g_ck[TOT];     // conv+silu outputs [b][c][s]
__device__ float g_cq[TOT];
__device__ float g_cv[TOT];
__device__ float g_kT[TOT];     // normalized, transposed [b][t][c]
__device__ float g_qT[TOT];
__device__ float g_vT[TOT];
__device__ float g_dT[TOT];     // delta output [b][t][c]
__device__ float g_normed[TOT]; // rms-normalized delta
__device__ float g_beta[MM];
__device__ float g_kq[MM];      // k_t . q_t per (b,t)
__device__ float g_ninv[2*512]; // inv l2 norms for k (0..511) and q (512..1023)

__device__ __forceinline__ float wsum(float v) {
    #pragma unroll
    for (int o = 16; o > 0; o >>= 1) v += __shfl_xor_sync(0xffffffffu, v, o);
    return v;
}

// ---------------- tf32 helpers ----------------
__device__ __forceinline__ unsigned f2tf32(float x) {
    unsigned r; asm("cvt.rna.tf32.f32 %0, %1;" : "=r"(r) : "f"(x)); return r;
}
__device__ __forceinline__ void mma_tf32(float c[4], const unsigned a[4],
                                         unsigned b0, unsigned b1) {
    asm("mma.sync.aligned.m16n8k8.row.col.f32.tf32.tf32.f32 "
        "{%0,%1,%2,%3}, {%4,%5,%6,%7}, {%8,%9}, {%0,%1,%2,%3};"
        : "+f"(c[0]), "+f"(c[1]), "+f"(c[2]), "+f"(c[3])
        : "r"(a[0]), "r"(a[1]), "r"(a[2]), "r"(a[3]), "r"(b0), "r"(b1));
}
__device__ __forceinline__ void split_sts4(unsigned* dH, unsigned* dL, float4 v) {
    uint4 h, l;
    h.x = f2tf32(v.x); l.x = f2tf32(v.x - __uint_as_float(h.x));
    h.y = f2tf32(v.y); l.y = f2tf32(v.y - __uint_as_float(h.y));
    h.z = f2tf32(v.z); l.z = f2tf32(v.z - __uint_as_float(h.z));
    h.w = f2tf32(v.w); l.w = f2tf32(v.w - __uint_as_float(h.w));
    *(uint4*)dH = h; *(uint4*)dL = l;
}

// =====================================================================
// 3xTF32 tensor-core GEMM core: block tile 128x128, 128 thr, 4 warps
// (2m x 2n), warp tile 64x64 (m16n8k8 tiles 4x8, 3 mma terms).
// LDS:HMMA = 64:96 per warp-ktile (1.5 ratio vs 1.0 before).
// BK=8, rows padded to 12 words (conflict-free), single smem buffer +
// register double-buffer (2 syncs/ktile), hi/lo tf32 split at staging.
// bias == nullptr -> raw store (split-K partial mode).
// =====================================================================
__device__ __forceinline__ void gemm3tf32_core_128x128(
    const float* __restrict__ A, int lda,
    const float* __restrict__ Bw, int ldb,
    const float* __restrict__ bias,
    float* __restrict__ C, int ldc,
    int m0, int nkt)
{
    __shared__ unsigned AsH[128*12], AsL[128*12];
    __shared__ unsigned BsH[128*12], BsL[128*12];

    const int tid  = threadIdx.x;
    const int w    = tid >> 5, lane = tid & 31;
    const int wm   = w & 1,  wn = w >> 1;
    const int g    = lane >> 2, tg = lane & 3;

    float acc[4][8][4];
    #pragma unroll
    for (int i = 0; i < 4; i++)
        #pragma unroll
        for (int j = 0; j < 8; j++)
            #pragma unroll
            for (int c = 0; c < 4; c++) acc[i][j][c] = 0.f;

    const float* arow = A + (size_t)(m0 + tid) * lda;
    const float* brow = Bw + (size_t)tid * ldb;

    float4 af0 = *(const float4*)(arow);
    float4 af1 = *(const float4*)(arow + 4);
    float4 bf0 = *(const float4*)(brow);
    float4 bf1 = *(const float4*)(brow + 4);

    for (int kt = 0; kt < nkt; ++kt) {
        __syncthreads();   // consumers of previous tile done
        split_sts4(&AsH[tid*12],     &AsL[tid*12],     af0);
        split_sts4(&AsH[tid*12 + 4], &AsL[tid*12 + 4], af1);
        split_sts4(&BsH[tid*12],     &BsL[tid*12],     bf0);
        split_sts4(&BsH[tid*12 + 4], &BsL[tid*12 + 4], bf1);
        __syncthreads();   // tile visible

        if (kt + 1 < nkt) {
            const float* ap = arow + (kt + 1) * 8;
            const float* bp = brow + (kt + 1) * 8;
            af0 = *(const float4*)(ap);
            af1 = *(const float4*)(ap + 4);
            bf0 = *(const float4*)(bp);
            bf1 = *(const float4*)(bp + 4);
        }

        // A fragments (hi & lo), 4 m16 tiles
        unsigned ah[4][4], al[4][4];
        #pragma unroll
        for (int i = 0; i < 4; i++) {
            int r0 = (wm*64 + i*16 + g) * 12 + tg;
            int r1 = r0 + 96;   // +8 rows
            ah[i][0] = AsH[r0];   ah[i][1] = AsH[r1];
            ah[i][2] = AsH[r0+4]; ah[i][3] = AsH[r1+4];
            al[i][0] = AsL[r0];   al[i][1] = AsL[r1];
            al[i][2] = AsL[r0+4]; al[i][3] = AsL[r1+4];
        }
        #pragma unroll
        for (int j = 0; j < 8; j++) {
            int nn = (wn*64 + j*8 + g) * 12 + tg;
            unsigned bh0 = BsH[nn], bh1 = BsH[nn+4];
            unsigned bl0 = BsL[nn], bl1 = BsL[nn+4];
            #pragma unroll
            for (int i = 0; i < 4; i++) {
                mma_tf32(acc[i][j], al[i], bh0, bh1);  // Alo*Bhi
                mma_tf32(acc[i][j], ah[i], bl0, bl1);  // Ahi*Blo
                mma_tf32(acc[i][j], ah[i], bh0, bh1);  // Ahi*Bhi
            }
        }
    }
    // epilogue
    #pragma unroll
    for (int i = 0; i < 4; i++) {
        const int r = m0 + wm*64 + i*16 + g;
        #pragma unroll
        for (int j = 0; j < 8; j++) {
            const int col = wn*64 + j*8 + tg*2;
            float b0v = 0.f, b1v = 0.f;
            if (bias) { b0v = bias[col]; b1v = bias[col + 1]; }
            float2 o0 = make_float2(acc[i][j][0] + b0v, acc[i][j][1] + b1v);
            float2 o1 = make_float2(acc[i][j][2] + b0v, acc[i][j][3] + b1v);
            *(float2*)(C + (size_t)r * ldc + col)       = o0;
            *(float2*)(C + (size_t)(r + 8) * ldc + col) = o1;
        }
    }
}

// Kernel 1: k/q/v projection GEMM, split-K=2. grid (3, 64, 2) x 128.
__global__ void __launch_bounds__(128) gemm_proj_tf32(
    const float* __restrict__ X,
    const float* __restrict__ Wk, const float* __restrict__ Wq, const float* __restrict__ Wv)
{
    const int sel = blockIdx.x;
    const int z   = blockIdx.z;
    const float* W = (sel == 0) ? Wk : (sel == 1) ? Wq : Wv;
    float* C       = g_psum[z][sel];
    gemm3tf32_core_128x128(X + z * 1024, 2048, W + z * 1024, 2048,
                           nullptr, C, 128, blockIdx.y * 128, 128);
}

// Kernel 1b: reduce split-K halves + bias. grid (1024, 3) x 256.
__global__ void __launch_bounds__(256) reduce_proj(
    const float* __restrict__ bk, const float* __restrict__ bq, const float* __restrict__ bv)
{
    const int sel = blockIdx.y;
    const float* bias = (sel == 0) ? bk : (sel == 1) ? bq : bv;
    float* out        = (sel == 0) ? g_pk : (sel == 1) ? g_pq : g_pv;
    const int i = blockIdx.x * 256 + threadIdx.x;
    float4 a = ((const float4*)g_psum[0][sel])[i];
    float4 b = ((const float4*)g_psum[1][sel])[i];
    float4 bi = ((const float4*)bias)[i & 31];
    float4 o;
    o.x = a.x + b.x + bi.x;
    o.y = a.y + b.y + bi.y;
    o.z = a.z + b.z + bi.z;
    o.w = a.w + b.w + bi.w;
    ((float4*)out)[i] = o;
}

// Kernel 8: output GEMM. grid (16, 64) x 128.
__global__ void __launch_bounds__(128) gemm_out_tf32(
    const float* __restrict__ Wo, const float* __restrict__ bo, float* __restrict__ OUT)
{
    const int n0 = blockIdx.x * 128;
    gemm3tf32_core_128x128(g_normed, 128, Wo + (size_t)n0 * 128, 128,
                           bo + n0, OUT + n0, 2048, blockIdx.y * 128, 16);
}

// =====================================================================
// Kernel 2: beta = sigmoid(x @ beta_w^T + beta_b). One warp per row.
// =====================================================================
__global__ void __launch_bounds__(128) beta_kernel(
    const float* __restrict__ X, const float* __restrict__ bw, const float* __restrict__ bb)
{
    const int m = blockIdx.x * 4 + (threadIdx.x >> 5);
    const int lane = threadIdx.x & 31;
    const float4* xr = (const float4*)(X + (size_t)m * 2048);
    const float4* wr = (const float4*)bw;
    float s = 0.f;
    #pragma unroll 4
    for (int i = 0; i < 16; i++) {
        float4 a = xr[i * 32 + lane];
        float4 w = wr[i * 32 + lane];
        s += a.x * w.x + a.y * w.y + a.z * w.z + a.w * w.w;
    }
    s = wsum(s);
    if (lane == 0) g_beta[m] = 1.f / (1.f + expf(-(s + bb[0])));
}

// =====================================================================
// Kernel 3: 1-D conv (k=3 over s, 128->128 ch) + bias + silu.
// =====================================================================
__global__ void __launch_bounds__(256) conv_silu(
    const float* __restrict__ wk, const float* __restrict__ bk,
    const float* __restrict__ wq, const float* __restrict__ bq,
    const float* __restrict__ wv, const float* __restrict__ bv)
{
    const int arr = blockIdx.z >> 2;
    const int b   = blockIdx.z & 3;
    const float* in  = (arr == 0) ? g_pk : (arr == 1) ? g_pq : g_pv;
    float* out       = (arr == 0) ? g_ck : (arr == 1) ? g_cq : g_cv;
    const float* w   = (arr == 0) ? wk : (arr == 1) ? wq : wv;
    const float* bias= (arr == 0) ? bk : (arr == 1) ? bq : bv;

    const int s0 = blockIdx.x * 128;
    const int o0 = blockIdx.y * 64;
    __shared__ float sin_[16][130];
    __shared__ float swt[64][16][3];
    const int tid = threadIdx.x;
    const int to = tid >> 4, ts = tid & 15;
    const int o_loc = to * 4, s_loc = ts * 8;
    const float* inb = in + (size_t)b * PER_B;

    float acc[4][8];
    #pragma unroll
    for (int oo = 0; oo < 4; oo++)
        #pragma unroll
        for (int ss = 0; ss < 8; ss++) acc[oo][ss] = 0.f;

    for (int ic = 0; ic < 8; ic++) {
        for (int i = tid; i < 2080; i += 256) {
            int j = i / 130, p = i % 130;
            int gs = s0 + p - 1;
            sin_[j][p] = (gs >= 0 && gs < 2048) ? inb[(ic * 16 + j) * 2048 + gs] : 0.f;
        }
        for (int i = tid; i < 3072; i += 256) {
            int o = i / 48, rr = i % 48, j = rr / 3, kh = rr % 3;
            swt[o][j][kh] = w[((size_t)(o0 + o) * 128 + ic * 16 + j) * 9 + kh * 3 + 1];
        }
        __syncthreads();
        #pragma unroll
        for (int j = 0; j < 16; j++) {
            float xin[10];
            #pragma unroll
            for (int p = 0; p < 10; p++) xin[p] = sin_[j][s_loc + p];
            #pragma unroll
            for (int oo = 0; oo < 4; oo++) {
                float w0 = swt[o_loc + oo][j][0];
                float w1 = swt[o_loc + oo][j][1];
                float w2 = swt[o_loc + oo][j][2];
                #pragma unroll
                for (int ss = 0; ss < 8; ss++)
                    acc[oo][ss] = fmaf(w0, xin[ss],
                                   fmaf(w1, xin[ss + 1],
                                    fmaf(w2, xin[ss + 2], acc[oo][ss])));
            }
        }
        __syncthreads();
    }
    float* outb = out + (size_t)b * PER_B;
    #pragma unroll
    for (int oo = 0; oo < 4; oo++) {
        float bvv = bias[o0 + o_loc + oo];
        float* orow = outb + (size_t)(o0 + o_loc + oo) * 2048 + s0 + s_loc;
        #pragma unroll
        for (int ss = 0; ss < 8; ss++) {
            float y = acc[oo][ss] + bvv;
            orow[ss] = y / (1.f + expf(-y));
        }
    }
}

// =====================================================================
// Kernel 4: inverse L2 norms over the s axis (2048) for k and q rows.
// =====================================================================
__global__ void __launch_bounds__(128) l2norms()
{
    const int arr = blockIdx.y;
    const int idx = blockIdx.x;
    const float* in = ((arr == 0) ? g_ck : g_cq) + (size_t)idx * 2048;
    const int tid = threadIdx.x;
    float ss = 0.f;
    const float4* in4 = (const float4*)in;
    for (int i = tid; i < 512; i += 128) {
        float4 v = in4[i];
        ss += v.x * v.x + v.y * v.y + v.z * v.z + v.w * v.w;
    }
    ss = wsum(ss);
    __shared__ float red[4];
    if ((tid & 31) == 0) red[tid >> 5] = ss;
    __syncthreads();
    if (tid == 0) {
        float tot = red[0] + red[1] + red[2] + red[3];
        g_ninv[arr * 512 + idx] = 1.f / fmaxf(sqrtf(tot), 1e-12f);
    }
}

// =====================================================================
// Kernel 5: scale (k,q) + transpose all three to [b][t][c].
// =====================================================================
__global__ void transpose_scale()
{
    const int z = blockIdx.z;
    const int arr = z >> 2, b = z & 3;
    const float* in = (arr == 0) ? g_ck : (arr == 1) ? g_cq : g_cv;
    float* out      = (arr == 0) ? g_kT : (arr == 1) ? g_qT : g_vT;
    const int s0 = blockIdx.x * 32, c0 = blockIdx.y * 32;
    __shared__ float tile[32][33];
    const int tx = threadIdx.x, ty = threadIdx.y;
    #pragma unroll
    for (int i = 0; i < 4; i++) {
        int c = c0 + ty + i * 8;
        float sc = (arr < 2) ? g_ninv[arr * 512 + b * 128 + c] : 1.f;
        tile[ty + i * 8][tx] = in[(size_t)b * PER_B + (size_t)c * 2048 + s0 + tx] * sc;
    }
    __syncthreads();
    #pragma unroll
    for (int i = 0; i < 4; i++) {
        int s = s0 + ty + i * 8;
        out[(size_t)b * PER_B + (size_t)s * 128 + c0 + tx] = tile[tx][ty + i * 8];
    }
}

// =====================================================================
// Kernel 5b: kq[m] = k_t . q_t (normalized). One warp per row.
// =====================================================================
__global__ void __launch_bounds__(128) kq_kernel()
{
    const int m = blockIdx.x * 4 + (threadIdx.x >> 5);
    const int lane = threadIdx.x & 31;
    const float* kr = g_kT + (size_t)m * 128;
    const float* qr = g_qT + (size_t)m * 128;
    float s = kr[lane] * qr[lane];
    s = fmaf(kr[lane + 32], qr[lane + 32], s);
    s = fmaf(kr[lane + 64], qr[lane + 64], s);
    s = fmaf(kr[lane + 96], qr[lane + 96], s);
    s = wsum(s);
    if (lane == 0) g_kq[m] = s;
}

// =====================================================================
// Kernel 6: delta rule. One warp per (b, row r); lane holds
// S[r][lane + 32j]. o_r = S_old[r].q + u_r*(k.q) keeps the two
// reductions independent -> interleaved shfl trees. 128 blocks x 128 thr.
// =====================================================================
__global__ void __launch_bounds__(128) delta_kernel()
{
    const int b  = blockIdx.x >> 5;
    const int rg = blockIdx.x & 31;
    const int warp = threadIdx.x >> 5;
    const int lane = threadIdx.x & 31;
    const int r = rg * 4 + warp;

    const float* kb = g_kT + (size_t)b * PER_B;
    const float* qb = g_qT + (size_t)b * PER_B;
    const float* vb = g_vT + (size_t)b * PER_B;
    const float* bbp = g_beta + b * 2048;
    const float* kqp = g_kq + b * 2048;
    float* ob = g_dT + (size_t)b * PER_B;

    float s0 = 0.f, s1 = 0.f, s2 = 0.f, s3 = 0.f;
    float kc0 = kb[lane], kc1 = kb[lane + 32], kc2 = kb[lane + 64], kc3 = kb[lane + 96];
    float qc0 = qb[lane], qc1 = qb[lane + 32], qc2 = qb[lane + 64], qc3 = qb[lane + 96];
    float vc = vb[r];
    float bc = bbp[0];
    float kqc = kqp[0];

    for (int t = 0; t < 2048; ++t) {
        float kn0 = 0, kn1 = 0, kn2 = 0, kn3 = 0, qn0 = 0, qn1 = 0, qn2 = 0, qn3 = 0;
        float vn = 0, bn = 0, kqn = 0;
        if (t < 2047) {
            const float* kp = kb + (size_t)(t + 1) * 128;
            const float* qp = qb + (size_t)(t + 1) * 128;
            kn0 = kp[lane]; kn1 = kp[lane + 32]; kn2 = kp[lane + 64]; kn3 = kp[lane + 96];
            qn0 = qp[lane]; qn1 = qp[lane + 32]; qn2 = qp[lane + 64]; qn3 = qp[lane + 96];
            vn = vb[(size_t)(t + 1) * 128 + r];
            bn = bbp[t + 1];
            kqn = kqp[t + 1];
        }
        float pa = fmaf(kc1, s1, kc0 * s0);
        float pb = fmaf(kc3, s3, kc2 * s2);
        float p  = pa + pb;
        float da = fmaf(qc1, s1, qc0 * s0);
        float db = fmaf(qc3, s3, qc2 * s2);
        float d  = da + db;
        #pragma unroll
        for (int o = 16; o > 0; o >>= 1) {
            p += __shfl_xor_sync(0xffffffffu, p, o);
            d += __shfl_xor_sync(0xffffffffu, d, o);
        }
        float u = bc * (vc - p);
        float oo = fmaf(u, kqc, d);
        if (lane == 0) ob[(size_t)t * 128 + r] = oo;
        s0 = fmaf(u, kc0, s0); s1 = fmaf(u, kc1, s1);
        s2 = fmaf(u, kc2, s2); s3 = fmaf(u, kc3, s3);

        kc0 = kn0; kc1 = kn1; kc2 = kn2; kc3 = kn3;
        qc0 = qn0; qc1 = qn1; qc2 = qn2; qc3 = qn3;
        vc = vn; bc = bn; kqc = kqn;
    }
}

// =====================================================================
// Kernel 7: RMS normalize delta over D * rms_w.
// =====================================================================
__global__ void __launch_bounds__(128) rms_kernel(const float* __restrict__ rms_w)
{
    const int m = blockIdx.x * 4 + (threadIdx.x >> 5);
    const int lane = threadIdx.x & 31;
    const float* row = g_dT + (size_t)m * 128;
    float v0 = row[lane], v1 = row[lane + 32], v2 = row[lane + 64], v3 = row[lane + 96];
    float ss = v0 * v0 + v1 * v1 + v2 * v2 + v3 * v3;
    ss = wsum(ss);
    float rs = 1.f / sqrtf(ss * (1.f / 128.f) + 1.1920928955078125e-07f);
    float* o = g_normed + (size_t)m * 128;
    o[lane]      = v0 * rs * rms_w[lane];
    o[lane + 32] = v1 * rs * rms_w[lane + 32];
    o[lane + 64] = v2 * rs * rms_w[lane + 64];
    o[lane + 96] = v3 * rs * rms_w[lane + 96];
}

// =====================================================================
extern "C" void kernel_launch(void* const* d_in, const int* in_sizes, int n_in,
                              void* d_out, int out_size)
{
    const float* x    = (const float*)d_in[0];
    const float* kpw  = (const float*)d_in[1];
    const float* kpb  = (const float*)d_in[2];
    const float* qpw  = (const float*)d_in[3];
    const float* qpb  = (const float*)d_in[4];
    const float* vpw  = (const float*)d_in[5];
    const float* vpb  = (const float*)d_in[6];
    const float* kcw  = (const float*)d_in[7];
    const float* kcb  = (const float*)d_in[8];
    const float* qcw  = (const float*)d_in[9];
    const float* qcb  = (const float*)d_in[10];
    const float* vcw  = (const float*)d_in[11];
    const float* vcb  = (const float*)d_in[12];
    const float* bw   = (const float*)d_in[13];
    const float* bb   = (const float*)d_in[14];
    const float* rmsw = (const float*)d_in[15];
    const float* ow   = (const float*)d_in[16];
    const float* obias= (const float*)d_in[17];
    float* out = (float*)d_out;

    // Order chosen so the ncu-profiled 4th launch is conv_silu (the
    // biggest unprofiled unknown).
    beta_kernel<<<2048, 128>>>(x, bw, bb);
    gemm_proj_tf32<<<dim3(3, 64, 2), 128>>>(x, kpw, qpw, vpw);
    reduce_proj<<<dim3(1024, 3), 256>>>(kpb, qpb, vpb);
    conv_silu<<<dim3(16, 2, 12), 256>>>(kcw, kcb, qcw, qcb, vcw, vcb);
    l2norms<<<dim3(512, 2), 128>>>();
    transpose_scale<<<dim3(64, 4, 12), dim3(32, 8)>>>();
    kq_kernel<<<2048, 128>>>();
    delta_kernel<<<128, 128>>>();
    rms_kernel<<<2048, 128>>>(rmsw);
    gemm_out_tf32<<<dim3(16, 64), 128>>>(ow, obias, out);
}

// round 9
// speedup vs baseline: 1.4931x; 1.3003x over previous
#include <cuda_runtime.h>
#include <math.h>

// ---------------- problem constants ----------------
#define BB 4
#define LL 2048
#define DD 128
#define MM (BB*LL)          // 8192 rows
#define PER_B (DD*LL)       // 262144 elements per batch per [D][L] buffer
#define TOT (BB*PER_B)      // 1048576

typedef unsigned long long u64;

// ---------------- scratch (static device memory; no allocation) ----------------
__device__ float g_pk[TOT];     // projection outputs [b][l][d] == conv input [b][c][s]
__device__ float g_pq[TOT];
__device__ float g_pv[TOT];
__device__ float g_psum[2][3][TOT]; // split-K partials [z][sel]
__device__ float g_ck[TOT];     // conv+silu outputs [b][c][s]
__device__ float g_cq[TOT];
__device__ float g_cv[TOT];
__device__ float g_kT[TOT];     // normalized, transposed [b][t][c]
__device__ float g_qT[TOT];
__device__ float g_vT[TOT];
__device__ float g_dT[TOT];     // delta output [b][t][c]
__device__ float g_normed[TOT]; // rms-normalized delta
__device__ float g_beta[MM];
__device__ float g_kq[MM];      // k_t . q_t per (b,t)
__device__ float g_ninv[2*512]; // inv l2 norms for k (0..511) and q (512..1023)

__device__ __forceinline__ float wsum(float v) {
    #pragma unroll
    for (int o = 16; o > 0; o >>= 1) v += __shfl_xor_sync(0xffffffffu, v, o);
    return v;
}

// ---------------- tf32 helpers ----------------
__device__ __forceinline__ unsigned f2tf32(float x) {
    unsigned r; asm("cvt.rna.tf32.f32 %0, %1;" : "=r"(r) : "f"(x)); return r;
}
__device__ __forceinline__ void mma_tf32(float c[4], const unsigned a[4],
                                         unsigned b0, unsigned b1) {
    asm("mma.sync.aligned.m16n8k8.row.col.f32.tf32.tf32.f32 "
        "{%0,%1,%2,%3}, {%4,%5,%6,%7}, {%8,%9}, {%0,%1,%2,%3};"
        : "+f"(c[0]), "+f"(c[1]), "+f"(c[2]), "+f"(c[3])
        : "r"(a[0]), "r"(a[1]), "r"(a[2]), "r"(a[3]), "r"(b0), "r"(b1));
}
__device__ __forceinline__ void split_sts4(unsigned* dH, unsigned* dL, float4 v) {
    uint4 h, l;
    h.x = f2tf32(v.x); l.x = f2tf32(v.x - __uint_as_float(h.x));
    h.y = f2tf32(v.y); l.y = f2tf32(v.y - __uint_as_float(h.y));
    h.z = f2tf32(v.z); l.z = f2tf32(v.z - __uint_as_float(h.z));
    h.w = f2tf32(v.w); l.w = f2tf32(v.w - __uint_as_float(h.w));
    *(uint4*)dH = h; *(uint4*)dL = l;
}

// =====================================================================
// 3xTF32 tensor-core GEMM core: block tile 128x128, 128 thr, 4 warps
// (2m x 2n), warp tile 64x64 (m16n8k8 tiles 4x8, 3 mma terms).
// BK=8, rows padded to 12 words, single smem buffer + register
// double-buffer (2 syncs/ktile), hi/lo tf32 split at staging.
// bias == nullptr -> raw store (split-K partial mode).
// =====================================================================
__device__ __forceinline__ void gemm3tf32_core_128x128(
    const float* __restrict__ A, int lda,
    const float* __restrict__ Bw, int ldb,
    const float* __restrict__ bias,
    float* __restrict__ C, int ldc,
    int m0, int nkt)
{
    __shared__ unsigned AsH[128*12], AsL[128*12];
    __shared__ unsigned BsH[128*12], BsL[128*12];

    const int tid  = threadIdx.x;
    const int w    = tid >> 5, lane = tid & 31;
    const int wm   = w & 1,  wn = w >> 1;
    const int g    = lane >> 2, tg = lane & 3;

    float acc[4][8][4];
    #pragma unroll
    for (int i = 0; i < 4; i++)
        #pragma unroll
        for (int j = 0; j < 8; j++)
            #pragma unroll
            for (int c = 0; c < 4; c++) acc[i][j][c] = 0.f;

    const float* arow = A + (size_t)(m0 + tid) * lda;
    const float* brow = Bw + (size_t)tid * ldb;

    float4 af0 = *(const float4*)(arow);
    float4 af1 = *(const float4*)(arow + 4);
    float4 bf0 = *(const float4*)(brow);
    float4 bf1 = *(const float4*)(brow + 4);

    for (int kt = 0; kt < nkt; ++kt) {
        __syncthreads();
        split_sts4(&AsH[tid*12],     &AsL[tid*12],     af0);
        split_sts4(&AsH[tid*12 + 4], &AsL[tid*12 + 4], af1);
        split_sts4(&BsH[tid*12],     &BsL[tid*12],     bf0);
        split_sts4(&BsH[tid*12 + 4], &BsL[tid*12 + 4], bf1);
        __syncthreads();

        if (kt + 1 < nkt) {
            const float* ap = arow + (kt + 1) * 8;
            const float* bp = brow + (kt + 1) * 8;
            af0 = *(const float4*)(ap);
            af1 = *(const float4*)(ap + 4);
            bf0 = *(const float4*)(bp);
            bf1 = *(const float4*)(bp + 4);
        }

        unsigned ah[4][4], al[4][4];
        #pragma unroll
        for (int i = 0; i < 4; i++) {
            int r0 = (wm*64 + i*16 + g) * 12 + tg;
            int r1 = r0 + 96;
            ah[i][0] = AsH[r0];   ah[i][1] = AsH[r1];
            ah[i][2] = AsH[r0+4]; ah[i][3] = AsH[r1+4];
            al[i][0] = AsL[r0];   al[i][1] = AsL[r1];
            al[i][2] = AsL[r0+4]; al[i][3] = AsL[r1+4];
        }
        #pragma unroll
        for (int j = 0; j < 8; j++) {
            int nn = (wn*64 + j*8 + g) * 12 + tg;
            unsigned bh0 = BsH[nn], bh1 = BsH[nn+4];
            unsigned bl0 = BsL[nn], bl1 = BsL[nn+4];
            #pragma unroll
            for (int i = 0; i < 4; i++) {
                mma_tf32(acc[i][j], al[i], bh0, bh1);
                mma_tf32(acc[i][j], ah[i], bl0, bl1);
                mma_tf32(acc[i][j], ah[i], bh0, bh1);
            }
        }
    }
    #pragma unroll
    for (int i = 0; i < 4; i++) {
        const int r = m0 + wm*64 + i*16 + g;
        #pragma unroll
        for (int j = 0; j < 8; j++) {
            const int col = wn*64 + j*8 + tg*2;
            float b0v = 0.f, b1v = 0.f;
            if (bias) { b0v = bias[col]; b1v = bias[col + 1]; }
            float2 o0 = make_float2(acc[i][j][0] + b0v, acc[i][j][1] + b1v);
            float2 o1 = make_float2(acc[i][j][2] + b0v, acc[i][j][3] + b1v);
            *(float2*)(C + (size_t)r * ldc + col)       = o0;
            *(float2*)(C + (size_t)(r + 8) * ldc + col) = o1;
        }
    }
}

// Kernel 1: k/q/v projection GEMM, split-K=2. grid (3, 64, 2) x 128.
__global__ void __launch_bounds__(128) gemm_proj_tf32(
    const float* __restrict__ X,
    const float* __restrict__ Wk, const float* __restrict__ Wq, const float* __restrict__ Wv)
{
    const int sel = blockIdx.x;
    const int z   = blockIdx.z;
    const float* W = (sel == 0) ? Wk : (sel == 1) ? Wq : Wv;
    float* C       = g_psum[z][sel];
    gemm3tf32_core_128x128(X + z * 1024, 2048, W + z * 1024, 2048,
                           nullptr, C, 128, blockIdx.y * 128, 128);
}

// Kernel 1b: reduce split-K halves + bias. grid (1024, 3) x 256.
__global__ void __launch_bounds__(256) reduce_proj(
    const float* __restrict__ bk, const float* __restrict__ bq, const float* __restrict__ bv)
{
    const int sel = blockIdx.y;
    const float* bias = (sel == 0) ? bk : (sel == 1) ? bq : bv;
    float* out        = (sel == 0) ? g_pk : (sel == 1) ? g_pq : g_pv;
    const int i = blockIdx.x * 256 + threadIdx.x;
    float4 a = ((const float4*)g_psum[0][sel])[i];
    float4 b = ((const float4*)g_psum[1][sel])[i];
    float4 bi = ((const float4*)bias)[i & 31];
    float4 o;
    o.x = a.x + b.x + bi.x;
    o.y = a.y + b.y + bi.y;
    o.z = a.z + b.z + bi.z;
    o.w = a.w + b.w + bi.w;
    ((float4*)out)[i] = o;
}

// Kernel 8: output GEMM. grid (16, 64) x 128.
__global__ void __launch_bounds__(128) gemm_out_tf32(
    const float* __restrict__ Wo, const float* __restrict__ bo, float* __restrict__ OUT)
{
    const int n0 = blockIdx.x * 128;
    gemm3tf32_core_128x128(g_normed, 128, Wo + (size_t)n0 * 128, 128,
                           bo + n0, OUT + n0, 2048, blockIdx.y * 128, 16);
}

// =====================================================================
// Kernel 2: beta = sigmoid(x @ beta_w^T + beta_b). One warp per row.
// =====================================================================
__global__ void __launch_bounds__(128) beta_kernel(
    const float* __restrict__ X, const float* __restrict__ bw, const float* __restrict__ bb,
    int m_off)
{
    const int m = m_off + blockIdx.x * 4 + (threadIdx.x >> 5);
    const int lane = threadIdx.x & 31;
    const float4* xr = (const float4*)(X + (size_t)m * 2048);
    const float4* wr = (const float4*)bw;
    float s = 0.f;
    #pragma unroll 4
    for (int i = 0; i < 16; i++) {
        float4 a = xr[i * 32 + lane];
        float4 w = wr[i * 32 + lane];
        s += a.x * w.x + a.y * w.y + a.z * w.z + a.w * w.w;
    }
    s = wsum(s);
    if (lane == 0) g_beta[m] = 1.f / (1.f + expf(-(s + bb[0])));
}

// =====================================================================
// Kernel 3: 1-D conv (k=3 over s, 128->128 ch) + bias + silu.
// =====================================================================
__global__ void __launch_bounds__(256) conv_silu(
    const float* __restrict__ wk, const float* __restrict__ bk,
    const float* __restrict__ wq, const float* __restrict__ bq,
    const float* __restrict__ wv, const float* __restrict__ bv)
{
    const int arr = blockIdx.z >> 2;
    const int b   = blockIdx.z & 3;
    const float* in  = (arr == 0) ? g_pk : (arr == 1) ? g_pq : g_pv;
    float* out       = (arr == 0) ? g_ck : (arr == 1) ? g_cq : g_cv;
    const float* w   = (arr == 0) ? wk : (arr == 1) ? wq : wv;
    const float* bias= (arr == 0) ? bk : (arr == 1) ? bq : bv;

    const int s0 = blockIdx.x * 128;
    const int o0 = blockIdx.y * 64;
    __shared__ float sin_[16][130];
    __shared__ float swt[64][16][3];
    const int tid = threadIdx.x;
    const int to = tid >> 4, ts = tid & 15;
    const int o_loc = to * 4, s_loc = ts * 8;
    const float* inb = in + (size_t)b * PER_B;

    float acc[4][8];
    #pragma unroll
    for (int oo = 0; oo < 4; oo++)
        #pragma unroll
        for (int ss = 0; ss < 8; ss++) acc[oo][ss] = 0.f;

    for (int ic = 0; ic < 8; ic++) {
        for (int i = tid; i < 2080; i += 256) {
            int j = i / 130, p = i % 130;
            int gs = s0 + p - 1;
            sin_[j][p] = (gs >= 0 && gs < 2048) ? inb[(ic * 16 + j) * 2048 + gs] : 0.f;
        }
        for (int i = tid; i < 3072; i += 256) {
            int o = i / 48, rr = i % 48, j = rr / 3, kh = rr % 3;
            swt[o][j][kh] = w[((size_t)(o0 + o) * 128 + ic * 16 + j) * 9 + kh * 3 + 1];
        }
        __syncthreads();
        #pragma unroll
        for (int j = 0; j < 16; j++) {
            float xin[10];
            #pragma unroll
            for (int p = 0; p < 10; p++) xin[p] = sin_[j][s_loc + p];
            #pragma unroll
            for (int oo = 0; oo < 4; oo++) {
                float w0 = swt[o_loc + oo][j][0];
                float w1 = swt[o_loc + oo][j][1];
                float w2 = swt[o_loc + oo][j][2];
                #pragma unroll
                for (int ss = 0; ss < 8; ss++)
                    acc[oo][ss] = fmaf(w0, xin[ss],
                                   fmaf(w1, xin[ss + 1],
                                    fmaf(w2, xin[ss + 2], acc[oo][ss])));
            }
        }
        __syncthreads();
    }
    float* outb = out + (size_t)b * PER_B;
    #pragma unroll
    for (int oo = 0; oo < 4; oo++) {
        float bvv = bias[o0 + o_loc + oo];
        float* orow = outb + (size_t)(o0 + o_loc + oo) * 2048 + s0 + s_loc;
        #pragma unroll
        for (int ss = 0; ss < 8; ss++) {
            float y = acc[oo][ss] + bvv;
            orow[ss] = y / (1.f + expf(-y));
        }
    }
}

// =====================================================================
// Kernel 4: inverse L2 norms over the s axis (2048) for k and q rows.
// =====================================================================
__global__ void __launch_bounds__(128) l2norms()
{
    const int arr = blockIdx.y;
    const int idx = blockIdx.x;
    const float* in = ((arr == 0) ? g_ck : g_cq) + (size_t)idx * 2048;
    const int tid = threadIdx.x;
    float ss = 0.f;
    const float4* in4 = (const float4*)in;
    for (int i = tid; i < 512; i += 128) {
        float4 v = in4[i];
        ss += v.x * v.x + v.y * v.y + v.z * v.z + v.w * v.w;
    }
    ss = wsum(ss);
    __shared__ float red[4];
    if ((tid & 31) == 0) red[tid >> 5] = ss;
    __syncthreads();
    if (tid == 0) {
        float tot = red[0] + red[1] + red[2] + red[3];
        g_ninv[arr * 512 + idx] = 1.f / fmaxf(sqrtf(tot), 1e-12f);
    }
}

// =====================================================================
// Kernel 5: scale (k,q) + transpose all three to [b][t][c].
// =====================================================================
__global__ void transpose_scale()
{
    const int z = blockIdx.z;
    const int arr = z >> 2, b = z & 3;
    const float* in = (arr == 0) ? g_ck : (arr == 1) ? g_cq : g_cv;
    float* out      = (arr == 0) ? g_kT : (arr == 1) ? g_qT : g_vT;
    const int s0 = blockIdx.x * 32, c0 = blockIdx.y * 32;
    __shared__ float tile[32][33];
    const int tx = threadIdx.x, ty = threadIdx.y;
    #pragma unroll
    for (int i = 0; i < 4; i++) {
        int c = c0 + ty + i * 8;
        float sc = (arr < 2) ? g_ninv[arr * 512 + b * 128 + c] : 1.f;
        tile[ty + i * 8][tx] = in[(size_t)b * PER_B + (size_t)c * 2048 + s0 + tx] * sc;
    }
    __syncthreads();
    #pragma unroll
    for (int i = 0; i < 4; i++) {
        int s = s0 + ty + i * 8;
        out[(size_t)b * PER_B + (size_t)s * 128 + c0 + tx] = tile[tx][ty + i * 8];
    }
}

// =====================================================================
// Kernel 5b: kq[m] = k_t . q_t (normalized). One warp per row.
// =====================================================================
__global__ void __launch_bounds__(128) kq_kernel()
{
    const int m = blockIdx.x * 4 + (threadIdx.x >> 5);
    const int lane = threadIdx.x & 31;
    const float* kr = g_kT + (size_t)m * 128;
    const float* qr = g_qT + (size_t)m * 128;
    float s = kr[lane] * qr[lane];
    s = fmaf(kr[lane + 32], qr[lane + 32], s);
    s = fmaf(kr[lane + 64], qr[lane + 64], s);
    s = fmaf(kr[lane + 96], qr[lane + 96], s);
    s = wsum(s);
    if (lane == 0) g_kq[m] = s;
}

// =====================================================================
// Kernel 6: delta rule, 32-lane rows + DEPTH-4 register ring prefetch.
// One warp per (b, row r); lane holds S[r][lane + 32j]. Loads for t+4
// are issued while computing t (4 x 165-cyc chain >> 262-cyc L2 lat).
// o_r = S_old[r].q + u_r*(k.q) keeps the two reductions independent.
// =====================================================================
__global__ void __launch_bounds__(128) delta_kernel()
{
    const int b  = blockIdx.x >> 5;
    const int rg = blockIdx.x & 31;
    const int warp = threadIdx.x >> 5;
    const int lane = threadIdx.x & 31;
    const int r = rg * 4 + warp;

    const float* kb = g_kT + (size_t)b * PER_B;
    const float* qb = g_qT + (size_t)b * PER_B;
    const float* vb = g_vT + (size_t)b * PER_B;
    const float* bbp = g_beta + b * 2048;
    const float* kqp = g_kq + b * 2048;
    float* ob = g_dT + (size_t)b * PER_B;

    float s0 = 0.f, s1 = 0.f, s2 = 0.f, s3 = 0.f;

    float kf[4][4], qf[4][4], vf[4], bf[4], kqf[4];
    #pragma unroll
    for (int j = 0; j < 4; j++) {
        const float* kp = kb + (size_t)j * 128;
        const float* qp = qb + (size_t)j * 128;
        kf[j][0] = kp[lane]; kf[j][1] = kp[lane + 32]; kf[j][2] = kp[lane + 64]; kf[j][3] = kp[lane + 96];
        qf[j][0] = qp[lane]; qf[j][1] = qp[lane + 32]; qf[j][2] = qp[lane + 64]; qf[j][3] = qp[lane + 96];
        vf[j]  = vb[(size_t)j * 128 + r];
        bf[j]  = bbp[j];
        kqf[j] = kqp[j];
    }

    for (int tb = 0; tb < 2048; tb += 4) {
        #pragma unroll
        for (int j = 0; j < 4; j++) {
            const int t = tb + j;
            // consume slot j
            float kc0 = kf[j][0], kc1 = kf[j][1], kc2 = kf[j][2], kc3 = kf[j][3];
            float qc0 = qf[j][0], qc1 = qf[j][1], qc2 = qf[j][2], qc3 = qf[j][3];
            float vc = vf[j], bc = bf[j], kqc = kqf[j];

            // refill slot j with t+4
            const int tn = t + 4;
            if (tn < 2048) {
                const float* kp = kb + (size_t)tn * 128;
                const float* qp = qb + (size_t)tn * 128;
                kf[j][0] = kp[lane]; kf[j][1] = kp[lane + 32]; kf[j][2] = kp[lane + 64]; kf[j][3] = kp[lane + 96];
                qf[j][0] = qp[lane]; qf[j][1] = qp[lane + 32]; qf[j][2] = qp[lane + 64]; qf[j][3] = qp[lane + 96];
                vf[j]  = vb[(size_t)tn * 128 + r];
                bf[j]  = bbp[tn];
                kqf[j] = kqp[tn];
            }

            float pa = fmaf(kc1, s1, kc0 * s0);
            float pb = fmaf(kc3, s3, kc2 * s2);
            float p  = pa + pb;
            float da = fmaf(qc1, s1, qc0 * s0);
            float db = fmaf(qc3, s3, qc2 * s2);
            float d  = da + db;
            #pragma unroll
            for (int o = 16; o > 0; o >>= 1) {
                p += __shfl_xor_sync(0xffffffffu, p, o);
                d += __shfl_xor_sync(0xffffffffu, d, o);
            }
            float u = bc * (vc - p);
            if (lane == 0) ob[(size_t)t * 128 + r] = fmaf(u, kqc, d);
            s0 = fmaf(u, kc0, s0); s1 = fmaf(u, kc1, s1);
            s2 = fmaf(u, kc2, s2); s3 = fmaf(u, kc3, s3);
        }
    }
}

// =====================================================================
// Kernel 7: RMS normalize delta over D * rms_w.
// =====================================================================
__global__ void __launch_bounds__(128) rms_kernel(const float* __restrict__ rms_w)
{
    const int m = blockIdx.x * 4 + (threadIdx.x >> 5);
    const int lane = threadIdx.x & 31;
    const float* row = g_dT + (size_t)m * 128;
    float v0 = row[lane], v1 = row[lane + 32], v2 = row[lane + 64], v3 = row[lane + 96];
    float ss = v0 * v0 + v1 * v1 + v2 * v2 + v3 * v3;
    ss = wsum(ss);
    float rs = 1.f / sqrtf(ss * (1.f / 128.f) + 1.1920928955078125e-07f);
    float* o = g_normed + (size_t)m * 128;
    o[lane]      = v0 * rs * rms_w[lane];
    o[lane + 32] = v1 * rs * rms_w[lane + 32];
    o[lane + 64] = v2 * rs * rms_w[lane + 64];
    o[lane + 96] = v3 * rs * rms_w[lane + 96];
}

// =====================================================================
extern "C" void kernel_launch(void* const* d_in, const int* in_sizes, int n_in,
                              void* d_out, int out_size)
{
    const float* x    = (const float*)d_in[0];
    const float* kpw  = (const float*)d_in[1];
    const float* kpb  = (const float*)d_in[2];
    const float* qpw  = (const float*)d_in[3];
    const float* qpb  = (const float*)d_in[4];
    const float* vpw  = (const float*)d_in[5];
    const float* vpb  = (const float*)d_in[6];
    const float* kcw  = (const float*)d_in[7];
    const float* kcb  = (const float*)d_in[8];
    const float* qcw  = (const float*)d_in[9];
    const float* qcb  = (const float*)d_in[10];
    const float* vcw  = (const float*)d_in[11];
    const float* vcb  = (const float*)d_in[12];
    const float* bw   = (const float*)d_in[13];
    const float* bb   = (const float*)d_in[14];
    const float* rmsw = (const float*)d_in[15];
    const float* ow   = (const float*)d_in[16];
    const float* obias= (const float*)d_in[17];
    float* out = (float*)d_out;

    // beta split x3 so the ncu-profiled 4th launch is gemm_proj_tf32
    // (need its tensor% at the 64x64 warp tile).
    beta_kernel<<<512, 128>>>(x, bw, bb, 0);
    beta_kernel<<<512, 128>>>(x, bw, bb, 2048);
    beta_kernel<<<1024, 128>>>(x, bw, bb, 4096);
    gemm_proj_tf32<<<dim3(3, 64, 2), 128>>>(x, kpw, qpw, vpw);
    reduce_proj<<<dim3(1024, 3), 256>>>(kpb, qpb, vpb);
    conv_silu<<<dim3(16, 2, 12), 256>>>(kcw, kcb, qcw, qcb, vcw, vcb);
    l2norms<<<dim3(512, 2), 128>>>();
    transpose_scale<<<dim3(64, 4, 12), dim3(32, 8)>>>();
    kq_kernel<<<2048, 128>>>();
    delta_kernel<<<128, 128>>>();
    rms_kernel<<<2048, 128>>>(rmsw);
    gemm_out_tf32<<<dim3(16, 64), 128>>>(ow, obias, out);
}